// round 1
// baseline (speedup 1.0000x reference)
#include <cuda_runtime.h>

#define NN 10000
#define NE 640000
#define D 128
#define H 8
#define DH 16

// ---------------- scratch (no allocations allowed) ----------------
__device__ float g_Q[NN * D];
__device__ float g_K[NN * D];
__device__ float g_V[NN * D];
__device__ float g_wV[NN * D];
__device__ float g_z[NN * H];

// ---------------- zero accumulators ----------------
__global__ void zero_kernel() {
    int i = blockIdx.x * blockDim.x + threadIdx.x;
    if (i < NN * D) g_wV[i] = 0.f;
    if (i < NN * H) g_z[i] = 0.f;
}

// ---------------- node projection GEMM: X[NN,128] @ W[128,128] ----------------
// blockIdx.y selects Q/K/V. 128x128 tile, BK=16, 256 threads, 8x8 microtile.
__global__ __launch_bounds__(256, 2)
void node_proj_kernel(const float* __restrict__ X,
                      const float* __restrict__ WQ,
                      const float* __restrict__ WK,
                      const float* __restrict__ WV) {
    const float* W = (blockIdx.y == 0) ? WQ : (blockIdx.y == 1) ? WK : WV;
    float* Out = (blockIdx.y == 0) ? g_Q : (blockIdx.y == 1) ? g_K : g_V;

    __shared__ float As[2][16][128];
    __shared__ float Bs[2][16][128];

    int tid = threadIdx.x;
    int ty = tid >> 4, tx = tid & 15;
    int rowBase = blockIdx.x << 7;

    // prologue: k-tile 0
#pragma unroll
    for (int it = 0; it < 2; ++it) {
        int lin = tid + (it << 8);
        int r = lin >> 2, c4 = (lin & 3) << 2;
        int gr = rowBase + r; if (gr >= NN) gr = NN - 1;
        float4 v = *(const float4*)&X[(size_t)gr * D + c4];
        As[0][c4 + 0][r] = v.x; As[0][c4 + 1][r] = v.y;
        As[0][c4 + 2][r] = v.z; As[0][c4 + 3][r] = v.w;
        int kr = lin >> 5, b4 = (lin & 31) << 2;
        *(float4*)&Bs[0][kr][b4] = *(const float4*)&W[kr * D + b4];
    }
    __syncthreads();

    float acc[8][8];
#pragma unroll
    for (int i = 0; i < 8; ++i)
#pragma unroll
        for (int j = 0; j < 8; ++j) acc[i][j] = 0.f;

#pragma unroll
    for (int kt = 0; kt < 8; ++kt) {
        int cur = kt & 1;
        float4 rA[2], rB[2];
        if (kt < 7) {
            int kB = (kt + 1) << 4;
#pragma unroll
            for (int it = 0; it < 2; ++it) {
                int lin = tid + (it << 8);
                int r = lin >> 2, c4 = (lin & 3) << 2;
                int gr = rowBase + r; if (gr >= NN) gr = NN - 1;
                rA[it] = *(const float4*)&X[(size_t)gr * D + kB + c4];
                int kr = lin >> 5, b4 = (lin & 31) << 2;
                rB[it] = *(const float4*)&W[(kB + kr) * D + b4];
            }
        }
#pragma unroll
        for (int kk = 0; kk < 16; ++kk) {
            float a[8], b[8];
            *(float4*)&a[0] = *(const float4*)&As[cur][kk][ty << 3];
            *(float4*)&a[4] = *(const float4*)&As[cur][kk][(ty << 3) + 4];
            *(float4*)&b[0] = *(const float4*)&Bs[cur][kk][tx << 3];
            *(float4*)&b[4] = *(const float4*)&Bs[cur][kk][(tx << 3) + 4];
#pragma unroll
            for (int i = 0; i < 8; ++i)
#pragma unroll
                for (int j = 0; j < 8; ++j)
                    acc[i][j] = fmaf(a[i], b[j], acc[i][j]);
        }
        if (kt < 7) {
            int nxt = cur ^ 1;
#pragma unroll
            for (int it = 0; it < 2; ++it) {
                int lin = tid + (it << 8);
                int r = lin >> 2, c4 = (lin & 3) << 2;
                As[nxt][c4 + 0][r] = rA[it].x; As[nxt][c4 + 1][r] = rA[it].y;
                As[nxt][c4 + 2][r] = rA[it].z; As[nxt][c4 + 3][r] = rA[it].w;
                int kr = lin >> 5, b4 = (lin & 31) << 2;
                *(float4*)&Bs[nxt][kr][b4] = rB[it];
            }
            __syncthreads();
        }
    }

    int c0 = tx << 3;
#pragma unroll
    for (int i = 0; i < 8; ++i) {
        int gr = rowBase + (ty << 3) + i;
        if (gr < NN) {
            *(float4*)&Out[(size_t)gr * D + c0] =
                make_float4(acc[i][0], acc[i][1], acc[i][2], acc[i][3]);
            *(float4*)&Out[(size_t)gr * D + c0 + 4] =
                make_float4(acc[i][4], acc[i][5], acc[i][6], acc[i][7]);
        }
    }
}

// ---------------- fused edge kernel ----------------
// proj_e = edge_feats @ We (tiled fp32 GEMM), then per-edge scoring epilogue:
//   score = clip(K[src]*Q[dst]*0.25, -5,5) * proj_e  -> e_out
//   s = exp(clip(sum_d score, -5,5))
//   red: wV[dst] += V[src]*s ; z[dst,h] += s
__global__ __launch_bounds__(256, 2)
void edge_kernel(const float* __restrict__ Ef, const float* __restrict__ We,
                 const int* __restrict__ src, const int* __restrict__ dst,
                 float* __restrict__ e_out) {
    __shared__ float As[2][16][128];
    __shared__ float Bs[2][16][128];
    __shared__ int s_src[128];
    __shared__ int s_dst[128];

    int tid = threadIdx.x;
    int ty = tid >> 4, tx = tid & 15;
    int rowBase = blockIdx.x << 7;   // E = 5000 * 128 exactly

    if (tid < 128) {
        s_src[tid] = src[rowBase + tid];
        s_dst[tid] = dst[rowBase + tid];
    }

#pragma unroll
    for (int it = 0; it < 2; ++it) {
        int lin = tid + (it << 8);
        int r = lin >> 2, c4 = (lin & 3) << 2;
        float4 v = *(const float4*)&Ef[(size_t)(rowBase + r) * D + c4];
        As[0][c4 + 0][r] = v.x; As[0][c4 + 1][r] = v.y;
        As[0][c4 + 2][r] = v.z; As[0][c4 + 3][r] = v.w;
        int kr = lin >> 5, b4 = (lin & 31) << 2;
        *(float4*)&Bs[0][kr][b4] = *(const float4*)&We[kr * D + b4];
    }
    __syncthreads();

    float acc[8][8];
#pragma unroll
    for (int i = 0; i < 8; ++i)
#pragma unroll
        for (int j = 0; j < 8; ++j) acc[i][j] = 0.f;

#pragma unroll
    for (int kt = 0; kt < 8; ++kt) {
        int cur = kt & 1;
        float4 rA[2], rB[2];
        if (kt < 7) {
            int kB = (kt + 1) << 4;
#pragma unroll
            for (int it = 0; it < 2; ++it) {
                int lin = tid + (it << 8);
                int r = lin >> 2, c4 = (lin & 3) << 2;
                rA[it] = *(const float4*)&Ef[(size_t)(rowBase + r) * D + kB + c4];
                int kr = lin >> 5, b4 = (lin & 31) << 2;
                rB[it] = *(const float4*)&We[(kB + kr) * D + b4];
            }
        }
#pragma unroll
        for (int kk = 0; kk < 16; ++kk) {
            float a[8], b[8];
            *(float4*)&a[0] = *(const float4*)&As[cur][kk][ty << 3];
            *(float4*)&a[4] = *(const float4*)&As[cur][kk][(ty << 3) + 4];
            *(float4*)&b[0] = *(const float4*)&Bs[cur][kk][tx << 3];
            *(float4*)&b[4] = *(const float4*)&Bs[cur][kk][(tx << 3) + 4];
#pragma unroll
            for (int i = 0; i < 8; ++i)
#pragma unroll
                for (int j = 0; j < 8; ++j)
                    acc[i][j] = fmaf(a[i], b[j], acc[i][j]);
        }
        if (kt < 7) {
            int nxt = cur ^ 1;
#pragma unroll
            for (int it = 0; it < 2; ++it) {
                int lin = tid + (it << 8);
                int r = lin >> 2, c4 = (lin & 3) << 2;
                As[nxt][c4 + 0][r] = rA[it].x; As[nxt][c4 + 1][r] = rA[it].y;
                As[nxt][c4 + 2][r] = rA[it].z; As[nxt][c4 + 3][r] = rA[it].w;
                int kr = lin >> 5, b4 = (lin & 31) << 2;
                *(float4*)&Bs[nxt][kr][b4] = rB[it];
            }
            __syncthreads();
        }
    }

    // ---- epilogue: scoring + scatter ----
    const float isd = 0.25f;   // 1/sqrt(16)
    int c0 = tx << 3;
    int h = tx >> 1;           // 8 cols lie fully inside one head (DH=16)

#pragma unroll
    for (int i = 0; i < 8; ++i) {
        int er = (ty << 3) + i;
        int e = rowBase + er;
        int sn = s_src[er], dn = s_dst[er];

        float4 k0 = *(const float4*)&g_K[sn * D + c0];
        float4 k1 = *(const float4*)&g_K[sn * D + c0 + 4];
        float4 q0 = *(const float4*)&g_Q[dn * D + c0];
        float4 q1 = *(const float4*)&g_Q[dn * D + c0 + 4];

        float kq[8];
        kq[0] = k0.x * q0.x; kq[1] = k0.y * q0.y; kq[2] = k0.z * q0.z; kq[3] = k0.w * q0.w;
        kq[4] = k1.x * q1.x; kq[5] = k1.y * q1.y; kq[6] = k1.z * q1.z; kq[7] = k1.w * q1.w;

        float sc[8];
        float part = 0.f;
#pragma unroll
        for (int j = 0; j < 8; ++j) {
            float t = fminf(fmaxf(kq[j] * isd, -5.f), 5.f);
            sc[j] = t * acc[i][j];
            part += sc[j];
        }

        *(float4*)&e_out[(size_t)e * D + c0] = make_float4(sc[0], sc[1], sc[2], sc[3]);
        *(float4*)&e_out[(size_t)e * D + c0 + 4] = make_float4(sc[4], sc[5], sc[6], sc[7]);

        // lanes tx and tx^1 (adjacent) cover the two halves of one head
        float tot = part + __shfl_xor_sync(0xffffffffu, part, 1);
        float s = __expf(fminf(fmaxf(tot, -5.f), 5.f));

        float4 v0 = *(const float4*)&g_V[sn * D + c0];
        float4 v1 = *(const float4*)&g_V[sn * D + c0 + 4];
        float* w = &g_wV[dn * D + c0];
        asm volatile("red.global.add.v4.f32 [%0], {%1,%2,%3,%4};"
                     :: "l"(w), "f"(v0.x * s), "f"(v0.y * s), "f"(v0.z * s), "f"(v0.w * s)
                     : "memory");
        asm volatile("red.global.add.v4.f32 [%0], {%1,%2,%3,%4};"
                     :: "l"(w + 4), "f"(v1.x * s), "f"(v1.y * s), "f"(v1.z * s), "f"(v1.w * s)
                     : "memory");
        if ((tx & 1) == 0)
            atomicAdd(&g_z[dn * H + h], s);
    }
}

// ---------------- normalize ----------------
__global__ void norm_kernel(float* __restrict__ h_out) {
    int i = blockIdx.x * blockDim.x + threadIdx.x;
    if (i < NN * D) {
        int n = i >> 7;
        int hh = (i & 127) >> 4;
        h_out[i] = g_wV[i] / (g_z[n * H + hh] + 1e-6f);
    }
}

// ---------------- launch ----------------
extern "C" void kernel_launch(void* const* d_in, const int* in_sizes, int n_in,
                              void* d_out, int out_size) {
    const float* node_feats = (const float*)d_in[0];
    const float* edge_feats = (const float*)d_in[1];
    const int* src = (const int*)d_in[2];
    const int* dst = (const int*)d_in[3];
    const float* WQ = (const float*)d_in[4];
    const float* WK = (const float*)d_in[5];
    const float* WV = (const float*)d_in[6];
    const float* We = (const float*)d_in[7];

    float* out = (float*)d_out;
    float* h_out = out;                 // [NN, H, DH]
    float* e_out = out + (size_t)NN * D; // [NE, H, DH]

    zero_kernel<<<(NN * D + 255) / 256, 256>>>();

    dim3 gn((NN + 127) / 128, 3);
    node_proj_kernel<<<gn, 256>>>(node_feats, WQ, WK, WV);

    edge_kernel<<<NE / 128, 256>>>(edge_feats, We, src, dst, e_out);

    norm_kernel<<<(NN * D + 255) / 256, 256>>>(h_out);
}

// round 3
// speedup vs baseline: 1.4713x; 1.4713x over previous
#include <cuda_runtime.h>
#include <cuda_bf16.h>
#include <cstdint>

#define NN 10000
#define NE 640000
#define D 128
#define H 8

// ---------------- scratch (no allocations allowed) ----------------
__device__ float g_Q[NN * D];
__device__ float g_K[NN * D];
__device__ float g_V[NN * D];
__device__ float g_wV[NN * D];
__device__ float g_z[NN * H];
// bf16 hi/lo images of We as B operand [n=128][k=128], 256B rows, XOR-swizzled 16B chunks
__device__ uint32_t g_Bhi[8192];
__device__ uint32_t g_Blo[8192];

__device__ __forceinline__ uint32_t smem_u32(const void* p) {
    uint32_t a;
    asm("{ .reg .u64 t; cvta.to.shared.u64 t, %1; cvt.u32.u64 %0, t; }" : "=r"(a) : "l"(p));
    return a;
}

#define LDSM4(r0, r1, r2, r3, a) \
    asm volatile("ldmatrix.sync.aligned.m8n8.x4.shared.b16 {%0,%1,%2,%3}, [%4];" \
        : "=r"(r0), "=r"(r1), "=r"(r2), "=r"(r3) : "r"(a))

#define MMA16816(c, a0, a1, a2, a3, b0, b1) \
    asm volatile("mma.sync.aligned.m16n8k16.row.col.f32.bf16.bf16.f32 " \
        "{%0,%1,%2,%3}, {%4,%5,%6,%7}, {%8,%9}, {%0,%1,%2,%3};" \
        : "+f"((c)[0]), "+f"((c)[1]), "+f"((c)[2]), "+f"((c)[3]) \
        : "r"(a0), "r"(a1), "r"(a2), "r"(a3), "r"(b0), "r"(b1))

// ---------------- zero accumulators ----------------
__global__ void zero_kernel() {
    int i = blockIdx.x * blockDim.x + threadIdx.x;
    if (i < NN * D) g_wV[i] = 0.f;
    if (i < NN * H) g_z[i] = 0.f;
}

// ---------------- prep B: We -> bf16 hi/lo swizzled images ----------------
// layout: row n (256B), 16B chunk u stores k-chunk c at u = c ^ (n&7)
__global__ void prep_B_kernel(const float* __restrict__ We) {
    int idx = blockIdx.x * 256 + threadIdx.x;  // 16384
    if (idx >= 16384) return;
    int k = idx >> 7, n = idx & 127;           // coalesced read We[k][n]
    float x = We[k * 128 + n];
    __nv_bfloat16 h = __float2bfloat16(x);
    __nv_bfloat16 l = __float2bfloat16(x - __bfloat162float(h));
    uint32_t off = (uint32_t)(n * 256 + (((k >> 3) ^ (n & 7)) * 16) + (k & 7) * 2);
    ((__nv_bfloat16*)g_Bhi)[off >> 1] = h;
    ((__nv_bfloat16*)g_Blo)[off >> 1] = l;
}

// ---------------- node projection GEMM (fp32, ~5% of work) ----------------
__global__ __launch_bounds__(256, 2)
void node_proj_kernel(const float* __restrict__ X,
                      const float* __restrict__ WQ,
                      const float* __restrict__ WK,
                      const float* __restrict__ WV) {
    const float* W = (blockIdx.y == 0) ? WQ : (blockIdx.y == 1) ? WK : WV;
    float* Out = (blockIdx.y == 0) ? g_Q : (blockIdx.y == 1) ? g_K : g_V;

    __shared__ float As[2][16][128];
    __shared__ float Bs[2][16][128];

    int tid = threadIdx.x;
    int ty = tid >> 4, tx = tid & 15;
    int rowBase = blockIdx.x << 7;

#pragma unroll
    for (int it = 0; it < 2; ++it) {
        int lin = tid + (it << 8);
        int r = lin >> 2, c4 = (lin & 3) << 2;
        int gr = rowBase + r; if (gr >= NN) gr = NN - 1;
        float4 v = *(const float4*)&X[(size_t)gr * D + c4];
        As[0][c4 + 0][r] = v.x; As[0][c4 + 1][r] = v.y;
        As[0][c4 + 2][r] = v.z; As[0][c4 + 3][r] = v.w;
        int kr = lin >> 5, b4 = (lin & 31) << 2;
        *(float4*)&Bs[0][kr][b4] = *(const float4*)&W[kr * D + b4];
    }
    __syncthreads();

    float acc[8][8];
#pragma unroll
    for (int i = 0; i < 8; ++i)
#pragma unroll
        for (int j = 0; j < 8; ++j) acc[i][j] = 0.f;

#pragma unroll
    for (int kt = 0; kt < 8; ++kt) {
        int cur = kt & 1;
        float4 rA[2], rB[2];
        if (kt < 7) {
            int kB = (kt + 1) << 4;
#pragma unroll
            for (int it = 0; it < 2; ++it) {
                int lin = tid + (it << 8);
                int r = lin >> 2, c4 = (lin & 3) << 2;
                int gr = rowBase + r; if (gr >= NN) gr = NN - 1;
                rA[it] = *(const float4*)&X[(size_t)gr * D + kB + c4];
                int kr = lin >> 5, b4 = (lin & 31) << 2;
                rB[it] = *(const float4*)&W[(kB + kr) * D + b4];
            }
        }
#pragma unroll
        for (int kk = 0; kk < 16; ++kk) {
            float a[8], b[8];
            *(float4*)&a[0] = *(const float4*)&As[cur][kk][ty << 3];
            *(float4*)&a[4] = *(const float4*)&As[cur][kk][(ty << 3) + 4];
            *(float4*)&b[0] = *(const float4*)&Bs[cur][kk][tx << 3];
            *(float4*)&b[4] = *(const float4*)&Bs[cur][kk][(tx << 3) + 4];
#pragma unroll
            for (int i = 0; i < 8; ++i)
#pragma unroll
                for (int j = 0; j < 8; ++j)
                    acc[i][j] = fmaf(a[i], b[j], acc[i][j]);
        }
        if (kt < 7) {
            int nxt = cur ^ 1;
#pragma unroll
            for (int it = 0; it < 2; ++it) {
                int lin = tid + (it << 8);
                int r = lin >> 2, c4 = (lin & 3) << 2;
                As[nxt][c4 + 0][r] = rA[it].x; As[nxt][c4 + 1][r] = rA[it].y;
                As[nxt][c4 + 2][r] = rA[it].z; As[nxt][c4 + 3][r] = rA[it].w;
                int kr = lin >> 5, b4 = (lin & 31) << 2;
                *(float4*)&Bs[nxt][kr][b4] = rB[it];
            }
            __syncthreads();
        }
    }

    int c0 = tx << 3;
#pragma unroll
    for (int i = 0; i < 8; ++i) {
        int gr = rowBase + (ty << 3) + i;
        if (gr < NN) {
            *(float4*)&Out[(size_t)gr * D + c0] =
                make_float4(acc[i][0], acc[i][1], acc[i][2], acc[i][3]);
            *(float4*)&Out[(size_t)gr * D + c0 + 4] =
                make_float4(acc[i][4], acc[i][5], acc[i][6], acc[i][7]);
        }
    }
}

// ---------------- fused edge kernel: bf16 mma.sync (3-pass split) + epilogue ----------------
// 256-edge tile, 8 warps, each warp = 32-row stripe (2 m16 blocks).
// smem: [0]   s_src[256]
//       [1024] s_dst[256]
//       [2048] A_hi (64KB) | A_lo (64KB) | B_hi (32KB) | B_lo (32KB)
//       Ds[256][132] f32 aliases A region after MMA.
#define SM_SRC  0
#define SM_DST  1024
#define SM_AHI  2048
#define SM_ALO  (SM_AHI + 65536)
#define SM_BHI  (SM_ALO + 65536)
#define SM_BLO  (SM_BHI + 32768)
#define SM_EDGE_TOTAL (SM_BLO + 32768)
#define DS_PITCH 132
#define TILE 256

__global__ __launch_bounds__(256, 1)
void edge_mma_kernel(const float* __restrict__ Ef,
                     const int* __restrict__ src, const int* __restrict__ dst,
                     float* __restrict__ e_out) {
    extern __shared__ char smem[];
    uint32_t sb = smem_u32(smem);
    int tid = threadIdx.x, wid = tid >> 5, lane = tid & 31;
    int rowBase = blockIdx.x << 8;

    if (tid < 256) {
        ((int*)(smem + SM_SRC))[tid] = src[rowBase + tid];
        ((int*)(smem + SM_DST))[tid] = dst[rowBase + tid];
    }

    // convert Ef tile (256 x 128 f32) into bf16 hi/lo swizzled images
#pragma unroll
    for (int rr = 0; rr < 2; ++rr) {
        int row = rr * 128 + (tid >> 1);
        int half = tid & 1;
        const float4* sp = (const float4*)&Ef[(size_t)(rowBase + row) * D + half * 64];
        uint32_t rbase = (uint32_t)(row * 256);
        int xr = row & 7;
#pragma unroll
        for (int i = 0; i < 8; ++i) {
            float4 v0 = sp[2 * i], v1 = sp[2 * i + 1];
            __nv_bfloat16 h[8], l[8];
            float f[8] = {v0.x, v0.y, v0.z, v0.w, v1.x, v1.y, v1.z, v1.w};
#pragma unroll
            for (int j = 0; j < 8; ++j) {
                h[j] = __float2bfloat16(f[j]);
                l[j] = __float2bfloat16(f[j] - __bfloat162float(h[j]));
            }
            int chunk = half * 8 + i;
            uint32_t off = rbase + (uint32_t)((chunk ^ xr) * 16);
            uint4 hv, lv;
            __nv_bfloat162 t;
            t = __nv_bfloat162(h[0], h[1]); hv.x = *(uint32_t*)&t;
            t = __nv_bfloat162(h[2], h[3]); hv.y = *(uint32_t*)&t;
            t = __nv_bfloat162(h[4], h[5]); hv.z = *(uint32_t*)&t;
            t = __nv_bfloat162(h[6], h[7]); hv.w = *(uint32_t*)&t;
            t = __nv_bfloat162(l[0], l[1]); lv.x = *(uint32_t*)&t;
            t = __nv_bfloat162(l[2], l[3]); lv.y = *(uint32_t*)&t;
            t = __nv_bfloat162(l[4], l[5]); lv.z = *(uint32_t*)&t;
            t = __nv_bfloat162(l[6], l[7]); lv.w = *(uint32_t*)&t;
            *(uint4*)(smem + SM_AHI + off) = hv;
            *(uint4*)(smem + SM_ALO + off) = lv;
        }
    }
    // copy pre-swizzled B images (32KB each)
    {
        const uint4* bh = (const uint4*)g_Bhi;
        const uint4* bl = (const uint4*)g_Blo;
        uint4* dh = (uint4*)(smem + SM_BHI);
        uint4* dl = (uint4*)(smem + SM_BLO);
#pragma unroll
        for (int i = tid; i < 2048; i += 256) { dh[i] = bh[i]; dl[i] = bl[i]; }
    }
    __syncthreads();

    // ---- 3-pass bf16 split GEMM: C = Ah*Bh + Ah*Bl + Al*Bh ----
    float c[2][16][4];
#pragma unroll
    for (int m = 0; m < 2; ++m)
#pragma unroll
        for (int n = 0; n < 16; ++n)
#pragma unroll
            for (int j = 0; j < 4; ++j) c[m][n][j] = 0.f;

    // A ldsm lane addressing: matrices [m0-7,c],[m8-15,c],[m0-7,c+1],[m8-15,c+1]
    int ar = wid * 32 + (lane & 7) + ((lane >> 3) & 1) * 8;
    int aco = lane >> 4;          // chunk offset 0/1
    int axr = ar & 7;
    uint32_t aRow0 = sb + (uint32_t)(ar * 256);          // mblk 0 (+SM_AHI later)
    // B ldsm lane addressing: [n0-7,c],[n0-7,c+1],[n8-15,c],[n8-15,c+1]
    int bnl = (lane & 7) + ((lane >> 4) << 3);           // 0..15 within nb-pair
    int bco = (lane >> 3) & 1;

    const uint32_t imgA[3] = {SM_AHI, SM_AHI, SM_ALO};
    const uint32_t imgB[3] = {SM_BHI, SM_BLO, SM_BHI};

#pragma unroll
    for (int p = 0; p < 3; ++p) {
        uint32_t Ab = aRow0 + imgA[p];
        uint32_t Bb = sb + imgB[p];
#pragma unroll
        for (int kb = 0; kb < 8; ++kb) {
            uint32_t au = (uint32_t)((2 * kb + aco) ^ axr) * 16;
            uint32_t a0[4], a1[4];
            LDSM4(a0[0], a0[1], a0[2], a0[3], Ab + au);
            LDSM4(a1[0], a1[1], a1[2], a1[3], Ab + 16 * 256 + au);
#pragma unroll
            for (int nb2 = 0; nb2 < 8; ++nb2) {
                int bn = nb2 * 16 + bnl;
                uint32_t bu = (uint32_t)((2 * kb + bco) ^ (bn & 7)) * 16;
                uint32_t b[4];
                LDSM4(b[0], b[1], b[2], b[3], Bb + (uint32_t)(bn * 256) + bu);
                MMA16816(c[0][2 * nb2 + 0], a0[0], a0[1], a0[2], a0[3], b[0], b[1]);
                MMA16816(c[0][2 * nb2 + 1], a0[0], a0[1], a0[2], a0[3], b[2], b[3]);
                MMA16816(c[1][2 * nb2 + 0], a1[0], a1[1], a1[2], a1[3], b[0], b[1]);
                MMA16816(c[1][2 * nb2 + 1], a1[0], a1[1], a1[2], a1[3], b[2], b[3]);
            }
        }
    }

    __syncthreads();   // all ldsm done before Ds aliases A/B region

    // stage C fragments -> Ds[256][132]
    float* Ds = (float*)(smem + SM_AHI);
    {
        int rq = lane >> 2, cq = (lane & 3) * 2;
#pragma unroll
        for (int m = 0; m < 2; ++m) {
            int r0 = wid * 32 + m * 16 + rq;
#pragma unroll
            for (int nb = 0; nb < 16; ++nb) {
                *(float2*)&Ds[r0 * DS_PITCH + nb * 8 + cq] = make_float2(c[m][nb][0], c[m][nb][1]);
                *(float2*)&Ds[(r0 + 8) * DS_PITCH + nb * 8 + cq] = make_float2(c[m][nb][2], c[m][nb][3]);
            }
        }
    }
    __syncthreads();

    // ---- epilogue (round-1 proven coalesced layout), 256 rows ----
    const float isd = 0.25f;
    int ty = tid >> 4, tx = tid & 15;
    int c0 = tx << 3;
    int h = tx >> 1;
    const int* s_src = (const int*)(smem + SM_SRC);
    const int* s_dst = (const int*)(smem + SM_DST);

#pragma unroll
    for (int i = 0; i < 16; ++i) {
        int er = ty * 16 + i;
        int e = rowBase + er;
        int sn = s_src[er], dn = s_dst[er];

        float4 k0 = *(const float4*)&g_K[sn * D + c0];
        float4 k1 = *(const float4*)&g_K[sn * D + c0 + 4];
        float4 q0 = *(const float4*)&g_Q[dn * D + c0];
        float4 q1 = *(const float4*)&g_Q[dn * D + c0 + 4];

        float kq[8];
        kq[0] = k0.x * q0.x; kq[1] = k0.y * q0.y; kq[2] = k0.z * q0.z; kq[3] = k0.w * q0.w;
        kq[4] = k1.x * q1.x; kq[5] = k1.y * q1.y; kq[6] = k1.z * q1.z; kq[7] = k1.w * q1.w;

        float pe[8];
        *(float4*)&pe[0] = *(const float4*)&Ds[er * DS_PITCH + c0];
        *(float4*)&pe[4] = *(const float4*)&Ds[er * DS_PITCH + c0 + 4];

        float sc[8];
        float part = 0.f;
#pragma unroll
        for (int j = 0; j < 8; ++j) {
            float t = fminf(fmaxf(kq[j] * isd, -5.f), 5.f);
            sc[j] = t * pe[j];
            part += sc[j];
        }

        *(float4*)&e_out[(size_t)e * D + c0] = make_float4(sc[0], sc[1], sc[2], sc[3]);
        *(float4*)&e_out[(size_t)e * D + c0 + 4] = make_float4(sc[4], sc[5], sc[6], sc[7]);

        float tot = part + __shfl_xor_sync(0xffffffffu, part, 1);
        float s = __expf(fminf(fmaxf(tot, -5.f), 5.f));

        float4 v0 = *(const float4*)&g_V[sn * D + c0];
        float4 v1 = *(const float4*)&g_V[sn * D + c0 + 4];
        float* w = &g_wV[dn * D + c0];
        asm volatile("red.global.add.v4.f32 [%0], {%1,%2,%3,%4};"
                     :: "l"(w), "f"(v0.x * s), "f"(v0.y * s), "f"(v0.z * s), "f"(v0.w * s)
                     : "memory");
        asm volatile("red.global.add.v4.f32 [%0], {%1,%2,%3,%4};"
                     :: "l"(w + 4), "f"(v1.x * s), "f"(v1.y * s), "f"(v1.z * s), "f"(v1.w * s)
                     : "memory");
        if ((tx & 1) == 0)
            atomicAdd(&g_z[dn * H + h], s);
    }
}

// ---------------- normalize ----------------
__global__ void norm_kernel(float* __restrict__ h_out) {
    int i = blockIdx.x * blockDim.x + threadIdx.x;
    if (i < NN * D) {
        int n = i >> 7;
        int hh = (i & 127) >> 4;
        h_out[i] = g_wV[i] / (g_z[n * H + hh] + 1e-6f);
    }
}

// ---------------- launch ----------------
extern "C" void kernel_launch(void* const* d_in, const int* in_sizes, int n_in,
                              void* d_out, int out_size) {
    const float* node_feats = (const float*)d_in[0];
    const float* edge_feats = (const float*)d_in[1];
    const int* src = (const int*)d_in[2];
    const int* dst = (const int*)d_in[3];
    const float* WQ = (const float*)d_in[4];
    const float* WK = (const float*)d_in[5];
    const float* WV = (const float*)d_in[6];
    const float* We = (const float*)d_in[7];

    float* out = (float*)d_out;
    float* h_out = out;                  // [NN, H, DH]
    float* e_out = out + (size_t)NN * D; // [NE, H, DH]

    static int smem_set = 0;
    if (!smem_set) {
        cudaFuncSetAttribute(edge_mma_kernel, cudaFuncAttributeMaxDynamicSharedMemorySize, SM_EDGE_TOTAL);
        smem_set = 1;
    }

    zero_kernel<<<(NN * D + 255) / 256, 256>>>();
    prep_B_kernel<<<64, 256>>>(We);

    dim3 gn((NN + 127) / 128, 3);
    node_proj_kernel<<<gn, 256>>>(node_feats, WQ, WK, WV);

    edge_mma_kernel<<<NE / TILE, 256, SM_EDGE_TOTAL>>>(edge_feats, src, dst, e_out);

    norm_kernel<<<(NN * D + 255) / 256, 256>>>(h_out);
}